// round 12
// baseline (speedup 1.0000x reference)
#include <cuda_runtime.h>
#include <cuda_bf16.h>
#include <cstdint>

#define B_       128
#define H3OUT    13
#define HW3      (H3OUT*H3OUT)     // 169
#define NROWS    (B_*HW3)          // 21632
#define NEMB     512
#define EMB      64
#define NCHUNK   8                 // vq code chunks

typedef unsigned long long ull;

// ---- packed fp32x2 helpers (vq) --------------------------------------------
__device__ __forceinline__ void fma2(ull& d, ull a, ull b) {
    asm("fma.rn.f32x2 %0, %1, %2, %0;" : "+l"(d) : "l"(a), "l"(b));
}
__device__ __forceinline__ float2 unpack2(ull v) {
    float2 r; asm("mov.b64 {%0, %1}, %2;" : "=f"(r.x), "=f"(r.y) : "l"(v)); return r;
}
union F4U { float4 f; ull u[2]; };

// ---- tf32 mma helpers -------------------------------------------------------
__device__ __forceinline__ uint32_t f2tf(float x) {
    uint32_t r; asm("cvt.rna.tf32.f32 %0, %1;" : "=r"(r) : "f"(x)); return r;
}
__device__ __forceinline__ void split2(float x, uint32_t& h, uint32_t& l) {
    h = f2tf(x);
    l = f2tf(x - __uint_as_float(h));
}
__device__ __forceinline__ void mma8(float* d, const uint32_t* a,
                                     uint32_t b0, uint32_t b1) {
    asm volatile("mma.sync.aligned.m16n8k8.row.col.f32.tf32.tf32.f32 "
        "{%0,%1,%2,%3}, {%4,%5,%6,%7}, {%8,%9}, {%0,%1,%2,%3};"
        : "+f"(d[0]), "+f"(d[1]), "+f"(d[2]), "+f"(d[3])
        : "r"(a[0]), "r"(a[1]), "r"(a[2]), "r"(a[3]), "r"(b0), "r"(b1));
}
// 3xTF32: hh + hl + lh   (ba = b0h,b1h,b0l,b1l)
__device__ __forceinline__ void mma3(float* d, const uint32_t* ah,
                                     const uint32_t* al, const uint4& ba) {
    mma8(d, ah, ba.x, ba.y);
    mma8(d, ah, ba.z, ba.w);
    mma8(d, al, ba.x, ba.y);
}
// flush RZ-chained mma acc into RN scalar acc, reset
__device__ __forceinline__ void flush4(float* s, float* d) {
    #pragma unroll
    for (int i = 0; i < 4; i++) { s[i] += d[i]; d[i] = 0.f; }
}

// ---- scratch ----------------------------------------------------------------
__device__ __align__(16) float g_z1[B_*48*48*64];          // NHWC
__device__ __align__(16) float g_z2n[B_*16*16*128];        // NHWC
__device__ __align__(16) float g_z3t[NROWS*EMB];
__device__ float g_vqs[NCHUNK*NROWS];
__device__ int   g_vqi[NCHUNK*NROWS];
__device__ uint4 g_B1f[24*8*32];       // (K=192,  N=64)
__device__ uint4 g_B2f[288*16*32];     // (K=2304, N=128)
__device__ uint4 g_B3f[256*8*32];      // (K=2048, N=64)

// ===========================================================================
// prep: pack weights into mma B fragments with tf32 2-way split (h,l)
// ===========================================================================
__global__ __launch_bounds__(256) void prep_kernel(
    const float* __restrict__ w1, const float* __restrict__ w2,
    const float* __restrict__ w3)
{
    int id = blockIdx.x*256 + threadIdx.x;
    if (id < 6144) {                       // conv1
        int l = id & 31, nt = (id >> 5) & 7, kc = id >> 8;
        int n = nt*8 + (l >> 2);
        int k0 = kc*8 + (l & 3);
        float v0 = w1[n*192 + k0];
        float v1 = w1[n*192 + k0 + 4];
        uint32_t h0, l0, h1, l1;
        split2(v0, h0, l0); split2(v1, h1, l1);
        g_B1f[id] = make_uint4(h0, h1, l0, l1);
        return;
    }
    id -= 6144;
    if (id < 147456) {                     // conv2: k = khkw*64 + ci
        int l = id & 31, nt = (id >> 5) & 15, kc = id >> 9;
        int n = nt*8 + (l >> 2);
        int k0 = kc*8 + (l & 3);
        int kh0 = k0 >> 6, ci0 = k0 & 63;
        int k1 = k0 + 4, kh1 = k1 >> 6, ci1 = k1 & 63;
        float v0 = w2[n*2304 + ci0*36 + kh0];
        float v1 = w2[n*2304 + ci1*36 + kh1];
        uint32_t h0, l0, h1, l1;
        split2(v0, h0, l0); split2(v1, h1, l1);
        g_B2f[id] = make_uint4(h0, h1, l0, l1);
        return;
    }
    id -= 147456;
    if (id < 65536) {                      // conv3: k = khkw*128 + ci
        int l = id & 31, nt = (id >> 5) & 7, kc = id >> 8;
        int n = nt*8 + (l >> 2);
        int k0 = kc*8 + (l & 3);
        int kh0 = k0 >> 7, ci0 = k0 & 127;
        int k1 = k0 + 4, kh1 = k1 >> 7, ci1 = k1 & 127;
        float v0 = w3[n*2048 + ci0*16 + kh0];
        float v1 = w3[n*2048 + ci1*16 + kh1];
        uint32_t h0, l0, h1, l1;
        split2(v0, h0, l0); split2(v1, h1, l1);
        g_B3f[id] = make_uint4(h0, h1, l0, l1);
    }
}

// ===========================================================================
// conv1 (mma): x * w1 s4 p2 +relu -> g_z1 NHWC; B double-buffered
// ===========================================================================
__global__ __launch_bounds__(256, 2) void conv1_mma(
    const float* __restrict__ x, const float* __restrict__ b1)
{
    __shared__ float patch[3][36][68];

    const int tile = blockIdx.x;
    const int b    = blockIdx.y;
    const int oh0  = (tile / 3) * 8;
    const int ow0  = (tile % 3) * 16;
    const int gy0  = oh0*4 - 2, gx0 = ow0*4 - 2;
    const int t    = threadIdx.x;

    for (int i = t; i < 3*36*68; i += 256) {
        int ci = i / 2448, rem = i % 2448;
        int iy = rem / 68, ix = rem % 68;
        int gy = gy0 + iy, gx = gx0 + ix;
        float v = 0.f;
        if (gy >= 0 && gy < 192 && gx >= 0 && gx < 192)
            v = x[((b*3 + ci)*192 + gy)*192 + gx];
        patch[ci][iy][ix] = v;
    }
    __syncthreads();

    const int warp = t >> 5, lane = t & 31;
    const int wm = warp & 3, wn = warp >> 2;
    const int gid = lane >> 2, tig = lane & 3;
    const int foff = wn*4;

    float acc[2][4][4], sac[2][4][4];
    #pragma unroll
    for (int mf = 0; mf < 2; mf++)
        #pragma unroll
        for (int nf = 0; nf < 4; nf++)
            #pragma unroll
            for (int i = 0; i < 4; i++) { acc[mf][nf][i] = 0.f; sac[mf][nf][i] = 0.f; }

    uint4 ba[2][4];
    #pragma unroll
    for (int nf = 0; nf < 4; nf++)
        ba[0][nf] = g_B1f[(foff + nf)*32 + lane];

    #pragma unroll 2
    for (int kc = 0; kc < 24; kc++) {
        const int cur = kc & 1;
        if (kc < 23) {
            #pragma unroll
            for (int nf = 0; nf < 4; nf++)
                ba[cur^1][nf] = g_B1f[((kc+1)*8 + foff + nf)*32 + lane];
        }
        const int ci = kc >> 3, kh = kc & 7;
        #pragma unroll
        for (int mf = 0; mf < 2; mf++) {
            const int sy = wm*2 + mf;
            const float* rowp = &patch[ci][sy*4 + kh][0];
            uint32_t ah[4], al[4];
            split2(rowp[gid*4 + tig],         ah[0], al[0]);
            split2(rowp[(gid+8)*4 + tig],     ah[1], al[1]);
            split2(rowp[gid*4 + tig + 4],     ah[2], al[2]);
            split2(rowp[(gid+8)*4 + tig + 4], ah[3], al[3]);
            #pragma unroll
            for (int nf = 0; nf < 4; nf++)
                mma3(acc[mf][nf], ah, al, ba[cur][nf]);
        }
        if ((kc & 7) == 7) {
            #pragma unroll
            for (int mf = 0; mf < 2; mf++)
                #pragma unroll
                for (int nf = 0; nf < 4; nf++)
                    flush4(sac[mf][nf], acc[mf][nf]);
        }
    }

    #pragma unroll
    for (int mf = 0; mf < 2; mf++) {
        const int oh = oh0 + wm*2 + mf;
        #pragma unroll
        for (int nf = 0; nf < 4; nf++) {
            const int n0 = wn*32 + nf*8 + 2*tig;
            float bb0 = __ldg(&b1[n0]), bb1 = __ldg(&b1[n0+1]);
            float2 v0 = make_float2(fmaxf(sac[mf][nf][0] + bb0, 0.f),
                                    fmaxf(sac[mf][nf][1] + bb1, 0.f));
            float2 v1 = make_float2(fmaxf(sac[mf][nf][2] + bb0, 0.f),
                                    fmaxf(sac[mf][nf][3] + bb1, 0.f));
            *(float2*)&g_z1[(((size_t)b*48 + oh)*48 + ow0 + gid    )*64 + n0] = v0;
            *(float2*)&g_z1[(((size_t)b*48 + oh)*48 + ow0 + gid + 8)*64 + n0] = v1;
        }
    }
}

// ===========================================================================
// conv2 (mma): M128 x N64 per block; grid 512; B double-buffered (i = kcb+c,
// kcb even -> buffer parity = c&1 is static under full c unroll).
// ===========================================================================
__global__ __launch_bounds__(256, 2) void conv2_mma(const float* __restrict__ b2)
{
    const int blk = blockIdx.x;
    const int b  = blk >> 2;
    const int mh = (blk >> 1) & 1;
    const int nh = blk & 1;
    const int t = threadIdx.x, warp = t >> 5, lane = t & 31;
    const int wm = warp & 3, wn = warp >> 2;
    const int gid = lane >> 2, tig = lane & 3;
    const int foff = nh*8 + wn*4;

    int ohA[2], owA[2], ohB[2], owB[2];
    #pragma unroll
    for (int mf = 0; mf < 2; mf++) {
        int p = mh*128 + wm*32 + mf*16 + gid;
        ohA[mf] = p >> 4; owA[mf] = p & 15;
        p += 8;
        ohB[mf] = p >> 4; owB[mf] = p & 15;
    }

    float acc[2][4][4], sac[2][4][4];
    #pragma unroll
    for (int mf = 0; mf < 2; mf++)
        #pragma unroll
        for (int nf = 0; nf < 4; nf++)
            #pragma unroll
            for (int i = 0; i < 4; i++) { acc[mf][nf][i] = 0.f; sac[mf][nf][i] = 0.f; }

    uint4 ba[2][4];
    #pragma unroll
    for (int nf = 0; nf < 4; nf++)
        ba[0][nf] = g_B2f[(foff + nf)*32 + lane];

    #pragma unroll 1
    for (int kh = 0; kh < 6; kh++) {
        #pragma unroll 1
        for (int kw = 0; kw < 6; kw++) {
            const float* pA[2]; const float* pB[2];
            bool vA[2], vB[2];
            #pragma unroll
            for (int mf = 0; mf < 2; mf++) {
                int y = ohA[mf]*3 - 2 + kh, xx = owA[mf]*3 - 2 + kw;
                vA[mf] = (y >= 0 && y < 48 && xx >= 0 && xx < 48);
                pA[mf] = &g_z1[(((size_t)b*48 + y)*48 + xx)*64];
                y = ohB[mf]*3 - 2 + kh; xx = owB[mf]*3 - 2 + kw;
                vB[mf] = (y >= 0 && y < 48 && xx >= 0 && xx < 48);
                pB[mf] = &g_z1[(((size_t)b*48 + y)*48 + xx)*64];
            }
            const int kcb = (kh*6 + kw)*8;
            #pragma unroll
            for (int c = 0; c < 8; c++) {
                const int i = kcb + c;
                const int cur = c & 1;           // kcb even -> static parity
                if (i < 287) {
                    #pragma unroll
                    for (int nf = 0; nf < 4; nf++)
                        ba[cur^1][nf] = g_B2f[((i+1)*16 + foff + nf)*32 + lane];
                }
                #pragma unroll
                for (int mf = 0; mf < 2; mf++) {
                    float a0 = vA[mf] ? pA[mf][c*8 + tig]     : 0.f;
                    float a1 = vB[mf] ? pB[mf][c*8 + tig]     : 0.f;
                    float a2 = vA[mf] ? pA[mf][c*8 + tig + 4] : 0.f;
                    float a3 = vB[mf] ? pB[mf][c*8 + tig + 4] : 0.f;
                    uint32_t ah[4], al[4];
                    split2(a0, ah[0], al[0]);
                    split2(a1, ah[1], al[1]);
                    split2(a2, ah[2], al[2]);
                    split2(a3, ah[3], al[3]);
                    #pragma unroll
                    for (int nf = 0; nf < 4; nf++)
                        mma3(acc[mf][nf], ah, al, ba[cur][nf]);
                }
            }
            #pragma unroll
            for (int mf = 0; mf < 2; mf++)
                #pragma unroll
                for (int nf = 0; nf < 4; nf++)
                    flush4(sac[mf][nf], acc[mf][nf]);
        }
    }

    #pragma unroll
    for (int mf = 0; mf < 2; mf++) {
        #pragma unroll
        for (int nf = 0; nf < 4; nf++) {
            const int n0 = nh*64 + wn*32 + nf*8 + 2*tig;
            float bb0 = __ldg(&b2[n0]), bb1 = __ldg(&b2[n0+1]);
            float2 v0 = make_float2(fmaxf(sac[mf][nf][0] + bb0, 0.f),
                                    fmaxf(sac[mf][nf][1] + bb1, 0.f));
            float2 v1 = make_float2(fmaxf(sac[mf][nf][2] + bb0, 0.f),
                                    fmaxf(sac[mf][nf][3] + bb1, 0.f));
            *(float2*)&g_z2n[(((size_t)b*16 + ohA[mf])*16 + owA[mf])*128 + n0] = v0;
            *(float2*)&g_z2n[(((size_t)b*16 + ohB[mf])*16 + owB[mf])*128 + n0] = v1;
        }
    }
}

// ===========================================================================
// conv3 (mma): M=64/block, grid 338; B double-buffered; A is L1-resident.
// ===========================================================================
__global__ __launch_bounds__(256, 2) void conv3_mma(const float* __restrict__ b3)
{
    const int t = threadIdx.x, warp = t >> 5, lane = t & 31;
    const int wm = warp >> 1, wn = warp & 1;
    const int gid = lane >> 2, tig = lane & 3;
    const int rbase = blockIdx.x*64 + wm*16;
    const int foff = wn*4;

    const int rA = rbase + gid, rB = rA + 8;
    const int bA = rA / HW3, spA = rA % HW3;
    const int y0A = spA / 13, x0A = spA % 13;
    const int bB = rB / HW3, spB = rB % HW3;
    const int y0B = spB / 13, x0B = spB % 13;

    float acc[4][4], sac[4][4];
    #pragma unroll
    for (int nf = 0; nf < 4; nf++)
        #pragma unroll
        for (int i = 0; i < 4; i++) { acc[nf][i] = 0.f; sac[nf][i] = 0.f; }

    uint4 ba[2][4];
    #pragma unroll
    for (int nf = 0; nf < 4; nf++)
        ba[0][nf] = g_B3f[(foff + nf)*32 + lane];

    #pragma unroll 1
    for (int kh = 0; kh < 4; kh++) {
        #pragma unroll 1
        for (int kw = 0; kw < 4; kw++) {
            const float* pA = &g_z2n[(((size_t)bA*16 + y0A + kh)*16 + x0A + kw)*128];
            const float* pB = &g_z2n[(((size_t)bB*16 + y0B + kh)*16 + x0B + kw)*128];
            const int kcb = (kh*4 + kw)*16;
            #pragma unroll
            for (int c = 0; c < 16; c++) {
                const int i = kcb + c;
                const int cur = c & 1;           // kcb even -> static parity
                if (i < 255) {
                    #pragma unroll
                    for (int nf = 0; nf < 4; nf++)
                        ba[cur^1][nf] = g_B3f[((i+1)*8 + foff + nf)*32 + lane];
                }
                uint32_t ah[4], al[4];
                split2(pA[c*8 + tig],     ah[0], al[0]);
                split2(pB[c*8 + tig],     ah[1], al[1]);
                split2(pA[c*8 + tig + 4], ah[2], al[2]);
                split2(pB[c*8 + tig + 4], ah[3], al[3]);
                #pragma unroll
                for (int nf = 0; nf < 4; nf++)
                    mma3(acc[nf], ah, al, ba[cur][nf]);
                if ((c & 7) == 7) {
                    #pragma unroll
                    for (int nf = 0; nf < 4; nf++)
                        flush4(sac[nf], acc[nf]);
                }
            }
        }
    }

    #pragma unroll
    for (int nf = 0; nf < 4; nf++) {
        const int n0 = wn*32 + nf*8 + 2*tig;
        float bb0 = __ldg(&b3[n0]), bb1 = __ldg(&b3[n0+1]);
        float2 v0 = make_float2(sac[nf][0] + bb0, sac[nf][1] + bb1);
        float2 v1 = make_float2(sac[nf][2] + bb0, sac[nf][3] + bb1);
        *(float2*)&g_z3t[(size_t)rA*EMB + n0] = v0;
        *(float2*)&g_z3t[(size_t)rB*EMB + n0] = v1;
    }
}

// ===========================================================================
// VQ partial argmin over 8 code chunks of 64: grid(85, 8), block 256.
// ===========================================================================
#define VQ_SMEM ((64*EMB + 64)*4)

__global__ __launch_bounds__(256, 2) void vq_kernel(const float* __restrict__ cb)
{
    extern __shared__ float sm[];
    float* cb_s = sm;
    float* cn_s = sm + 64*EMB;

    const int chunk = blockIdx.y;
    const int t = threadIdx.x;

    for (int idx = t; idx < 64*EMB; idx += 256)
        cb_s[idx] = cb[chunk*64*EMB + idx];
    __syncthreads();
    if (t < 64) {
        float s = 0.f;
        const float* cp = &cb_s[t*EMB];
        #pragma unroll 8
        for (int j = 0; j < EMB; j++) s += cp[j]*cp[j];
        cn_s[t] = s;
    }
    __syncthreads();

    const int row = blockIdx.x*256 + t;
    if (row >= NROWS) return;

    ull zu[32];
    const float4* zp = (const float4*)&g_z3t[row*EMB];
    #pragma unroll
    for (int i = 0; i < 16; i++) {
        F4U v; v.f = zp[i];
        zu[2*i] = v.u[0]; zu[2*i+1] = v.u[1];
    }

    float best = 3.402823466e38f;
    int bi = 0;
    for (int k = 0; k < 64; k++) {
        const float4* cp = (const float4*)&cb_s[k*EMB];
        ull d0 = 0ull, d1 = 0ull, d2 = 0ull, d3 = 0ull;
        #pragma unroll
        for (int i = 0; i < 8; i++) {
            F4U ca; ca.f = cp[2*i];
            F4U cb2; cb2.f = cp[2*i+1];
            fma2(d0, ca.u[0],  zu[4*i]);
            fma2(d1, ca.u[1],  zu[4*i+1]);
            fma2(d2, cb2.u[0], zu[4*i+2]);
            fma2(d3, cb2.u[1], zu[4*i+3]);
        }
        float2 s0 = unpack2(d0), s1 = unpack2(d1), s2 = unpack2(d2), s3 = unpack2(d3);
        float dot = ((s0.x+s0.y) + (s1.x+s1.y)) + ((s2.x+s2.y) + (s3.x+s3.y));
        float score = cn_s[k] - 2.f*dot;
        if (score < best) { best = score; bi = k; }
    }
    g_vqs[chunk*NROWS + row] = best;
    g_vqi[chunk*NROWS + row] = chunk*64 + bi;
}

// ===========================================================================
// output: zero-fill + merge-8 argmin scatter
// ===========================================================================
__global__ __launch_bounds__(256) void zero_kernel(float4* __restrict__ out4)
{
    int idx = blockIdx.x*256 + threadIdx.x;
    float4 z = make_float4(0.f, 0.f, 0.f, 0.f);
    #pragma unroll
    for (int i = 0; i < 8; i++)
        out4[idx + i*(1352*256)] = z;
}

__global__ __launch_bounds__(256) void scatter_kernel(float* __restrict__ out)
{
    int row = blockIdx.x*256 + threadIdx.x;
    if (row >= NROWS) return;
    float best = g_vqs[row];
    int bi = g_vqi[row];
    #pragma unroll
    for (int c = 1; c < NCHUNK; c++) {
        float s = g_vqs[c*NROWS + row];
        int i2 = g_vqi[c*NROWS + row];
        if (s < best) { best = s; bi = i2; }
    }
    int b = row / HW3, hw = row % HW3;
    out[((size_t)(b*NEMB + bi))*HW3 + hw] = 1.0f;
}

// ===========================================================================
extern "C" void kernel_launch(void* const* d_in, const int* in_sizes, int n_in,
                              void* d_out, int out_size)
{
    const float* x  = (const float*)d_in[0];
    const float* w1 = (const float*)d_in[1];
    const float* b1 = (const float*)d_in[2];
    const float* w2 = (const float*)d_in[3];
    const float* b2 = (const float*)d_in[4];
    const float* w3 = (const float*)d_in[5];
    const float* b3 = (const float*)d_in[6];
    const float* cb = (const float*)d_in[7];
    float* out = (float*)d_out;

    cudaFuncSetAttribute(vq_kernel, cudaFuncAttributeMaxDynamicSharedMemorySize, VQ_SMEM);

    prep_kernel<<<856, 256>>>(w1, w2, w3);
    conv1_mma<<<dim3(18, B_), 256>>>(x, b1);
    conv2_mma<<<512, 256>>>(b2);
    conv3_mma<<<338, 256>>>(b3);
    vq_kernel<<<dim3(85, NCHUNK), 256, VQ_SMEM>>>(cb);
    zero_kernel<<<1352, 256>>>((float4*)out);
    scatter_kernel<<<85, 256>>>(out);
}

// round 13
// speedup vs baseline: 1.0019x; 1.0019x over previous
#include <cuda_runtime.h>
#include <cuda_bf16.h>
#include <cstdint>

#define B_       128
#define H3OUT    13
#define HW3      (H3OUT*H3OUT)     // 169
#define NROWS    (B_*HW3)          // 21632
#define NEMB     512
#define EMB      64
#define NCHUNK   8                 // vq code chunks

typedef unsigned long long ull;

// ---- packed fp32x2 helpers (vq) --------------------------------------------
__device__ __forceinline__ void fma2(ull& d, ull a, ull b) {
    asm("fma.rn.f32x2 %0, %1, %2, %0;" : "+l"(d) : "l"(a), "l"(b));
}
__device__ __forceinline__ float2 unpack2(ull v) {
    float2 r; asm("mov.b64 {%0, %1}, %2;" : "=f"(r.x), "=f"(r.y) : "l"(v)); return r;
}
union F4U { float4 f; ull u[2]; };

// ---- tf32 mma helpers -------------------------------------------------------
__device__ __forceinline__ uint32_t f2tf(float x) {
    uint32_t r; asm("cvt.rna.tf32.f32 %0, %1;" : "=r"(r) : "f"(x)); return r;
}
__device__ __forceinline__ void split2(float x, uint32_t& h, uint32_t& l) {
    h = f2tf(x);
    l = f2tf(x - __uint_as_float(h));
}
__device__ __forceinline__ void mma8(float* d, const uint32_t* a,
                                     uint32_t b0, uint32_t b1) {
    asm volatile("mma.sync.aligned.m16n8k8.row.col.f32.tf32.tf32.f32 "
        "{%0,%1,%2,%3}, {%4,%5,%6,%7}, {%8,%9}, {%0,%1,%2,%3};"
        : "+f"(d[0]), "+f"(d[1]), "+f"(d[2]), "+f"(d[3])
        : "r"(a[0]), "r"(a[1]), "r"(a[2]), "r"(a[3]), "r"(b0), "r"(b1));
}
// 3xTF32: hh + hl + lh   (ba = b0h,b1h,b0l,b1l)
__device__ __forceinline__ void mma3(float* d, const uint32_t* ah,
                                     const uint32_t* al, const uint4& ba) {
    mma8(d, ah, ba.x, ba.y);
    mma8(d, ah, ba.z, ba.w);
    mma8(d, al, ba.x, ba.y);
}
// flush RZ-chained mma acc into RN scalar acc, reset
__device__ __forceinline__ void flush4(float* s, float* d) {
    #pragma unroll
    for (int i = 0; i < 4; i++) { s[i] += d[i]; d[i] = 0.f; }
}

// ---- scratch ----------------------------------------------------------------
__device__ __align__(16) float g_z1[B_*48*48*64];          // NHWC
__device__ __align__(16) float g_z2n[B_*16*16*128];        // NHWC
__device__ __align__(16) float g_z3t[NROWS*EMB];
__device__ float g_vqs[NCHUNK*NROWS];
__device__ int   g_vqi[NCHUNK*NROWS];
__device__ uint4 g_B1f[24*8*32];       // (K=192,  N=64)
__device__ uint4 g_B2f[288*16*32];     // (K=2304, N=128)
__device__ uint4 g_B3f[256*8*32];      // (K=2048, N=64)

// ===========================================================================
// prep: pack weights into mma B fragments with tf32 2-way split (h,l)
// ===========================================================================
__global__ __launch_bounds__(256) void prep_kernel(
    const float* __restrict__ w1, const float* __restrict__ w2,
    const float* __restrict__ w3)
{
    int id = blockIdx.x*256 + threadIdx.x;
    if (id < 6144) {                       // conv1
        int l = id & 31, nt = (id >> 5) & 7, kc = id >> 8;
        int n = nt*8 + (l >> 2);
        int k0 = kc*8 + (l & 3);
        float v0 = w1[n*192 + k0];
        float v1 = w1[n*192 + k0 + 4];
        uint32_t h0, l0, h1, l1;
        split2(v0, h0, l0); split2(v1, h1, l1);
        g_B1f[id] = make_uint4(h0, h1, l0, l1);
        return;
    }
    id -= 6144;
    if (id < 147456) {                     // conv2: k = khkw*64 + ci
        int l = id & 31, nt = (id >> 5) & 15, kc = id >> 9;
        int n = nt*8 + (l >> 2);
        int k0 = kc*8 + (l & 3);
        int kh0 = k0 >> 6, ci0 = k0 & 63;
        int k1 = k0 + 4, kh1 = k1 >> 6, ci1 = k1 & 63;
        float v0 = w2[n*2304 + ci0*36 + kh0];
        float v1 = w2[n*2304 + ci1*36 + kh1];
        uint32_t h0, l0, h1, l1;
        split2(v0, h0, l0); split2(v1, h1, l1);
        g_B2f[id] = make_uint4(h0, h1, l0, l1);
        return;
    }
    id -= 147456;
    if (id < 65536) {                      // conv3: k = khkw*128 + ci
        int l = id & 31, nt = (id >> 5) & 7, kc = id >> 8;
        int n = nt*8 + (l >> 2);
        int k0 = kc*8 + (l & 3);
        int kh0 = k0 >> 7, ci0 = k0 & 127;
        int k1 = k0 + 4, kh1 = k1 >> 7, ci1 = k1 & 127;
        float v0 = w3[n*2048 + ci0*16 + kh0];
        float v1 = w3[n*2048 + ci1*16 + kh1];
        uint32_t h0, l0, h1, l1;
        split2(v0, h0, l0); split2(v1, h1, l1);
        g_B3f[id] = make_uint4(h0, h1, l0, l1);
    }
}

// ===========================================================================
// conv1 (mma): x * w1 s4 p2 +relu -> g_z1 NHWC; B double-buffered
// ===========================================================================
__global__ __launch_bounds__(256, 2) void conv1_mma(
    const float* __restrict__ x, const float* __restrict__ b1)
{
    __shared__ float patch[3][36][68];

    const int tile = blockIdx.x;
    const int b    = blockIdx.y;
    const int oh0  = (tile / 3) * 8;
    const int ow0  = (tile % 3) * 16;
    const int gy0  = oh0*4 - 2, gx0 = ow0*4 - 2;
    const int t    = threadIdx.x;

    for (int i = t; i < 3*36*68; i += 256) {
        int ci = i / 2448, rem = i % 2448;
        int iy = rem / 68, ix = rem % 68;
        int gy = gy0 + iy, gx = gx0 + ix;
        float v = 0.f;
        if (gy >= 0 && gy < 192 && gx >= 0 && gx < 192)
            v = x[((b*3 + ci)*192 + gy)*192 + gx];
        patch[ci][iy][ix] = v;
    }
    __syncthreads();

    const int warp = t >> 5, lane = t & 31;
    const int wm = warp & 3, wn = warp >> 2;
    const int gid = lane >> 2, tig = lane & 3;
    const int foff = wn*4;

    float acc[2][4][4], sac[2][4][4];
    #pragma unroll
    for (int mf = 0; mf < 2; mf++)
        #pragma unroll
        for (int nf = 0; nf < 4; nf++)
            #pragma unroll
            for (int i = 0; i < 4; i++) { acc[mf][nf][i] = 0.f; sac[mf][nf][i] = 0.f; }

    uint4 ba[2][4];
    #pragma unroll
    for (int nf = 0; nf < 4; nf++)
        ba[0][nf] = g_B1f[(foff + nf)*32 + lane];

    #pragma unroll 2
    for (int kc = 0; kc < 24; kc++) {
        const int cur = kc & 1;
        if (kc < 23) {
            #pragma unroll
            for (int nf = 0; nf < 4; nf++)
                ba[cur^1][nf] = g_B1f[((kc+1)*8 + foff + nf)*32 + lane];
        }
        const int ci = kc >> 3, kh = kc & 7;
        #pragma unroll
        for (int mf = 0; mf < 2; mf++) {
            const int sy = wm*2 + mf;
            const float* rowp = &patch[ci][sy*4 + kh][0];
            uint32_t ah[4], al[4];
            split2(rowp[gid*4 + tig],         ah[0], al[0]);
            split2(rowp[(gid+8)*4 + tig],     ah[1], al[1]);
            split2(rowp[gid*4 + tig + 4],     ah[2], al[2]);
            split2(rowp[(gid+8)*4 + tig + 4], ah[3], al[3]);
            #pragma unroll
            for (int nf = 0; nf < 4; nf++)
                mma3(acc[mf][nf], ah, al, ba[cur][nf]);
        }
        if ((kc & 7) == 7) {
            #pragma unroll
            for (int mf = 0; mf < 2; mf++)
                #pragma unroll
                for (int nf = 0; nf < 4; nf++)
                    flush4(sac[mf][nf], acc[mf][nf]);
        }
    }

    #pragma unroll
    for (int mf = 0; mf < 2; mf++) {
        const int oh = oh0 + wm*2 + mf;
        #pragma unroll
        for (int nf = 0; nf < 4; nf++) {
            const int n0 = wn*32 + nf*8 + 2*tig;
            float bb0 = __ldg(&b1[n0]), bb1 = __ldg(&b1[n0+1]);
            float2 v0 = make_float2(fmaxf(sac[mf][nf][0] + bb0, 0.f),
                                    fmaxf(sac[mf][nf][1] + bb1, 0.f));
            float2 v1 = make_float2(fmaxf(sac[mf][nf][2] + bb0, 0.f),
                                    fmaxf(sac[mf][nf][3] + bb1, 0.f));
            *(float2*)&g_z1[(((size_t)b*48 + oh)*48 + ow0 + gid    )*64 + n0] = v0;
            *(float2*)&g_z1[(((size_t)b*48 + oh)*48 + ow0 + gid + 8)*64 + n0] = v1;
        }
    }
}

// ===========================================================================
// conv2 (mma): M128 x N64 per block; grid 512; B double-buffered (i = kcb+c,
// kcb even -> buffer parity = c&1 is static under full c unroll).
// ===========================================================================
__global__ __launch_bounds__(256, 2) void conv2_mma(const float* __restrict__ b2)
{
    const int blk = blockIdx.x;
    const int b  = blk >> 2;
    const int mh = (blk >> 1) & 1;
    const int nh = blk & 1;
    const int t = threadIdx.x, warp = t >> 5, lane = t & 31;
    const int wm = warp & 3, wn = warp >> 2;
    const int gid = lane >> 2, tig = lane & 3;
    const int foff = nh*8 + wn*4;

    int ohA[2], owA[2], ohB[2], owB[2];
    #pragma unroll
    for (int mf = 0; mf < 2; mf++) {
        int p = mh*128 + wm*32 + mf*16 + gid;
        ohA[mf] = p >> 4; owA[mf] = p & 15;
        p += 8;
        ohB[mf] = p >> 4; owB[mf] = p & 15;
    }

    float acc[2][4][4], sac[2][4][4];
    #pragma unroll
    for (int mf = 0; mf < 2; mf++)
        #pragma unroll
        for (int nf = 0; nf < 4; nf++)
            #pragma unroll
            for (int i = 0; i < 4; i++) { acc[mf][nf][i] = 0.f; sac[mf][nf][i] = 0.f; }

    uint4 ba[2][4];
    #pragma unroll
    for (int nf = 0; nf < 4; nf++)
        ba[0][nf] = g_B2f[(foff + nf)*32 + lane];

    #pragma unroll 1
    for (int kh = 0; kh < 6; kh++) {
        #pragma unroll 1
        for (int kw = 0; kw < 6; kw++) {
            const float* pA[2]; const float* pB[2];
            bool vA[2], vB[2];
            #pragma unroll
            for (int mf = 0; mf < 2; mf++) {
                int y = ohA[mf]*3 - 2 + kh, xx = owA[mf]*3 - 2 + kw;
                vA[mf] = (y >= 0 && y < 48 && xx >= 0 && xx < 48);
                pA[mf] = &g_z1[(((size_t)b*48 + y)*48 + xx)*64];
                y = ohB[mf]*3 - 2 + kh; xx = owB[mf]*3 - 2 + kw;
                vB[mf] = (y >= 0 && y < 48 && xx >= 0 && xx < 48);
                pB[mf] = &g_z1[(((size_t)b*48 + y)*48 + xx)*64];
            }
            const int kcb = (kh*6 + kw)*8;
            #pragma unroll
            for (int c = 0; c < 8; c++) {
                const int i = kcb + c;
                const int cur = c & 1;           // kcb even -> static parity
                if (i < 287) {
                    #pragma unroll
                    for (int nf = 0; nf < 4; nf++)
                        ba[cur^1][nf] = g_B2f[((i+1)*16 + foff + nf)*32 + lane];
                }
                #pragma unroll
                for (int mf = 0; mf < 2; mf++) {
                    float a0 = vA[mf] ? pA[mf][c*8 + tig]     : 0.f;
                    float a1 = vB[mf] ? pB[mf][c*8 + tig]     : 0.f;
                    float a2 = vA[mf] ? pA[mf][c*8 + tig + 4] : 0.f;
                    float a3 = vB[mf] ? pB[mf][c*8 + tig + 4] : 0.f;
                    uint32_t ah[4], al[4];
                    split2(a0, ah[0], al[0]);
                    split2(a1, ah[1], al[1]);
                    split2(a2, ah[2], al[2]);
                    split2(a3, ah[3], al[3]);
                    #pragma unroll
                    for (int nf = 0; nf < 4; nf++)
                        mma3(acc[mf][nf], ah, al, ba[cur][nf]);
                }
            }
            #pragma unroll
            for (int mf = 0; mf < 2; mf++)
                #pragma unroll
                for (int nf = 0; nf < 4; nf++)
                    flush4(sac[mf][nf], acc[mf][nf]);
        }
    }

    #pragma unroll
    for (int mf = 0; mf < 2; mf++) {
        #pragma unroll
        for (int nf = 0; nf < 4; nf++) {
            const int n0 = nh*64 + wn*32 + nf*8 + 2*tig;
            float bb0 = __ldg(&b2[n0]), bb1 = __ldg(&b2[n0+1]);
            float2 v0 = make_float2(fmaxf(sac[mf][nf][0] + bb0, 0.f),
                                    fmaxf(sac[mf][nf][1] + bb1, 0.f));
            float2 v1 = make_float2(fmaxf(sac[mf][nf][2] + bb0, 0.f),
                                    fmaxf(sac[mf][nf][3] + bb1, 0.f));
            *(float2*)&g_z2n[(((size_t)b*16 + ohA[mf])*16 + owA[mf])*128 + n0] = v0;
            *(float2*)&g_z2n[(((size_t)b*16 + ohB[mf])*16 + owB[mf])*128 + n0] = v1;
        }
    }
}

// ===========================================================================
// conv3 (mma): M=64/block, grid 338; B double-buffered; A is L1-resident.
// ===========================================================================
__global__ __launch_bounds__(256, 2) void conv3_mma(const float* __restrict__ b3)
{
    const int t = threadIdx.x, warp = t >> 5, lane = t & 31;
    const int wm = warp >> 1, wn = warp & 1;
    const int gid = lane >> 2, tig = lane & 3;
    const int rbase = blockIdx.x*64 + wm*16;
    const int foff = wn*4;

    const int rA = rbase + gid, rB = rA + 8;
    const int bA = rA / HW3, spA = rA % HW3;
    const int y0A = spA / 13, x0A = spA % 13;
    const int bB = rB / HW3, spB = rB % HW3;
    const int y0B = spB / 13, x0B = spB % 13;

    float acc[4][4], sac[4][4];
    #pragma unroll
    for (int nf = 0; nf < 4; nf++)
        #pragma unroll
        for (int i = 0; i < 4; i++) { acc[nf][i] = 0.f; sac[nf][i] = 0.f; }

    uint4 ba[2][4];
    #pragma unroll
    for (int nf = 0; nf < 4; nf++)
        ba[0][nf] = g_B3f[(foff + nf)*32 + lane];

    #pragma unroll 1
    for (int kh = 0; kh < 4; kh++) {
        #pragma unroll 1
        for (int kw = 0; kw < 4; kw++) {
            const float* pA = &g_z2n[(((size_t)bA*16 + y0A + kh)*16 + x0A + kw)*128];
            const float* pB = &g_z2n[(((size_t)bB*16 + y0B + kh)*16 + x0B + kw)*128];
            const int kcb = (kh*4 + kw)*16;
            #pragma unroll
            for (int c = 0; c < 16; c++) {
                const int i = kcb + c;
                const int cur = c & 1;           // kcb even -> static parity
                if (i < 255) {
                    #pragma unroll
                    for (int nf = 0; nf < 4; nf++)
                        ba[cur^1][nf] = g_B3f[((i+1)*8 + foff + nf)*32 + lane];
                }
                uint32_t ah[4], al[4];
                split2(pA[c*8 + tig],     ah[0], al[0]);
                split2(pB[c*8 + tig],     ah[1], al[1]);
                split2(pA[c*8 + tig + 4], ah[2], al[2]);
                split2(pB[c*8 + tig + 4], ah[3], al[3]);
                #pragma unroll
                for (int nf = 0; nf < 4; nf++)
                    mma3(acc[nf], ah, al, ba[cur][nf]);
                if ((c & 7) == 7) {
                    #pragma unroll
                    for (int nf = 0; nf < 4; nf++)
                        flush4(sac[nf], acc[nf]);
                }
            }
        }
    }

    #pragma unroll
    for (int nf = 0; nf < 4; nf++) {
        const int n0 = wn*32 + nf*8 + 2*tig;
        float bb0 = __ldg(&b3[n0]), bb1 = __ldg(&b3[n0+1]);
        float2 v0 = make_float2(sac[nf][0] + bb0, sac[nf][1] + bb1);
        float2 v1 = make_float2(sac[nf][2] + bb0, sac[nf][3] + bb1);
        *(float2*)&g_z3t[(size_t)rA*EMB + n0] = v0;
        *(float2*)&g_z3t[(size_t)rB*EMB + n0] = v1;
    }
}

// ===========================================================================
// VQ partial argmin over 8 code chunks of 64: grid(85, 8), block 256.
// ===========================================================================
#define VQ_SMEM ((64*EMB + 64)*4)

__global__ __launch_bounds__(256, 2) void vq_kernel(const float* __restrict__ cb)
{
    extern __shared__ float sm[];
    float* cb_s = sm;
    float* cn_s = sm + 64*EMB;

    const int chunk = blockIdx.y;
    const int t = threadIdx.x;

    for (int idx = t; idx < 64*EMB; idx += 256)
        cb_s[idx] = cb[chunk*64*EMB + idx];
    __syncthreads();
    if (t < 64) {
        float s = 0.f;
        const float* cp = &cb_s[t*EMB];
        #pragma unroll 8
        for (int j = 0; j < EMB; j++) s += cp[j]*cp[j];
        cn_s[t] = s;
    }
    __syncthreads();

    const int row = blockIdx.x*256 + t;
    if (row >= NROWS) return;

    ull zu[32];
    const float4* zp = (const float4*)&g_z3t[row*EMB];
    #pragma unroll
    for (int i = 0; i < 16; i++) {
        F4U v; v.f = zp[i];
        zu[2*i] = v.u[0]; zu[2*i+1] = v.u[1];
    }

    float best = 3.402823466e38f;
    int bi = 0;
    for (int k = 0; k < 64; k++) {
        const float4* cp = (const float4*)&cb_s[k*EMB];
        ull d0 = 0ull, d1 = 0ull, d2 = 0ull, d3 = 0ull;
        #pragma unroll
        for (int i = 0; i < 8; i++) {
            F4U ca; ca.f = cp[2*i];
            F4U cb2; cb2.f = cp[2*i+1];
            fma2(d0, ca.u[0],  zu[4*i]);
            fma2(d1, ca.u[1],  zu[4*i+1]);
            fma2(d2, cb2.u[0], zu[4*i+2]);
            fma2(d3, cb2.u[1], zu[4*i+3]);
        }
        float2 s0 = unpack2(d0), s1 = unpack2(d1), s2 = unpack2(d2), s3 = unpack2(d3);
        float dot = ((s0.x+s0.y) + (s1.x+s1.y)) + ((s2.x+s2.y) + (s3.x+s3.y));
        float score = cn_s[k] - 2.f*dot;
        if (score < best) { best = score; bi = k; }
    }
    g_vqs[chunk*NROWS + row] = best;
    g_vqi[chunk*NROWS + row] = chunk*64 + bi;
}

// ===========================================================================
// output: zero-fill + merge-8 argmin scatter
// ===========================================================================
__global__ __launch_bounds__(256) void zero_kernel(float4* __restrict__ out4)
{
    int idx = blockIdx.x*256 + threadIdx.x;
    float4 z = make_float4(0.f, 0.f, 0.f, 0.f);
    #pragma unroll
    for (int i = 0; i < 8; i++)
        out4[idx + i*(1352*256)] = z;
}

__global__ __launch_bounds__(256) void scatter_kernel(float* __restrict__ out)
{
    int row = blockIdx.x*256 + threadIdx.x;
    if (row >= NROWS) return;
    float best = g_vqs[row];
    int bi = g_vqi[row];
    #pragma unroll
    for (int c = 1; c < NCHUNK; c++) {
        float s = g_vqs[c*NROWS + row];
        int i2 = g_vqi[c*NROWS + row];
        if (s < best) { best = s; bi = i2; }
    }
    int b = row / HW3, hw = row % HW3;
    out[((size_t)(b*NEMB + bi))*HW3 + hw] = 1.0f;
}

// ===========================================================================
extern "C" void kernel_launch(void* const* d_in, const int* in_sizes, int n_in,
                              void* d_out, int out_size)
{
    const float* x  = (const float*)d_in[0];
    const float* w1 = (const float*)d_in[1];
    const float* b1 = (const float*)d_in[2];
    const float* w2 = (const float*)d_in[3];
    const float* b2 = (const float*)d_in[4];
    const float* w3 = (const float*)d_in[5];
    const float* b3 = (const float*)d_in[6];
    const float* cb = (const float*)d_in[7];
    float* out = (float*)d_out;

    cudaFuncSetAttribute(vq_kernel, cudaFuncAttributeMaxDynamicSharedMemorySize, VQ_SMEM);

    prep_kernel<<<856, 256>>>(w1, w2, w3);
    conv1_mma<<<dim3(18, B_), 256>>>(x, b1);
    conv2_mma<<<512, 256>>>(b2);
    conv3_mma<<<338, 256>>>(b3);
    vq_kernel<<<dim3(85, NCHUNK), 256, VQ_SMEM>>>(cb);
    zero_kernel<<<1352, 256>>>((float4*)out);
    scatter_kernel<<<85, 256>>>(out);
}